// round 6
// baseline (speedup 1.0000x reference)
#include <cuda_runtime.h>
#include <cuda_bf16.h>
#include <cstdint>

// ---------------------------------------------------------------------------
// ConditionedConvolution2D via mma.sync bf16 (3-term split, fp32 accumulate)
//   X [32,128,128,32] f32 NHWC, P [32,128] f32, dense_w [128,9216] f32
//   A = P @ dense_w -> Wk[32,3,3,32,32];  out[b] = conv2d_same(X[b], Wk[b])
// x = xh + xl (bf16), w = wh + wl (bf16); out ~= xh*wh + xh*wl + xl*wh.
// ---------------------------------------------------------------------------

#define B_       32
#define HW_      128
#define WK_PER_B 9216
#define FRAG_B   36864      // bytes of packed bf16 B-fragments per batch
#define XROW_SMEM 16640     // 130 px * 128 B (hi|lo * 32 ci bf16)
#define SMEM_TOTAL (4 * XROW_SMEM)   // 66560

__device__ unsigned char g_wfrag[B_ * FRAG_B];

// SW128 swizzle (row stride 128B): XOR bits[4:6] with bits[7:9]
#define SWZ(o) ((o) ^ (((o) >> 3) & 0x70))

__device__ __forceinline__ uint32_t smem_u32(const void* p) {
    uint32_t a;
    asm("{ .reg .u64 t; cvta.to.shared.u64 t, %1; cvt.u32.u64 %0, t; }"
        : "=r"(a) : "l"(p));
    return a;
}
__device__ __forceinline__ void ldsm4(uint32_t* r, uint32_t addr) {
    asm volatile("ldmatrix.sync.aligned.m8n8.x4.shared.b16 {%0,%1,%2,%3}, [%4];"
        : "=r"(r[0]), "=r"(r[1]), "=r"(r[2]), "=r"(r[3]) : "r"(addr));
}
__device__ __forceinline__ void hmma(float* c, const uint32_t* a, const uint32_t* b) {
    asm volatile("mma.sync.aligned.m16n8k16.row.col.f32.bf16.bf16.f32 "
        "{%0,%1,%2,%3}, {%4,%5,%6,%7}, {%8,%9}, {%0,%1,%2,%3};"
        : "+f"(c[0]), "+f"(c[1]), "+f"(c[2]), "+f"(c[3])
        : "r"(a[0]), "r"(a[1]), "r"(a[2]), "r"(a[3]), "r"(b[0]), "r"(b[1]));
}
__device__ __forceinline__ uint32_t pk(__nv_bfloat16 a, __nv_bfloat16 b) {
    return (uint32_t)__bfloat16_as_ushort(a) | ((uint32_t)__bfloat16_as_ushort(b) << 16);
}
__device__ __forceinline__ void split4(float4 v, uint2& h, uint2& l) {
    __nv_bfloat16 hx = __float2bfloat16_rn(v.x), hy = __float2bfloat16_rn(v.y);
    __nv_bfloat16 hz = __float2bfloat16_rn(v.z), hw = __float2bfloat16_rn(v.w);
    h.x = pk(hx, hy); h.y = pk(hz, hw);
    l.x = pk(__float2bfloat16_rn(v.x - __bfloat162float(hx)),
             __float2bfloat16_rn(v.y - __bfloat162float(hy)));
    l.y = pk(__float2bfloat16_rn(v.z - __bfloat162float(hz)),
             __float2bfloat16_rn(v.w - __bfloat162float(hw)));
}

// ---------------------------------------------------------------------------
// Kernel 1: hypernetwork GEMM; writes wh/wl bf16 directly in mma-B fragment
// layout:  g_wfrag[b][tap][ws][n][lane][4 x u32]
// grid (36, 4), 256 threads; each block handles 8 batches.
// ---------------------------------------------------------------------------
__global__ __launch_bounds__(256)
void wgemm_kernel(const float* __restrict__ P, const float* __restrict__ Dw) {
    __shared__ float sp[1024];
    const int b0 = blockIdx.y * 8;
    const int j  = blockIdx.x * 256 + threadIdx.x;    // 0..9215

    for (int i = threadIdx.x; i < 1024; i += 256) sp[i] = P[b0 * 128 + i];
    __syncthreads();

    float acc[8];
#pragma unroll
    for (int bb = 0; bb < 8; ++bb) acc[bb] = 0.f;

    const float* dcol = Dw + j;
    // k-loop unrolled by 16: 16 independent strided LDGs in flight
#pragma unroll
    for (int k0 = 0; k0 < 128; k0 += 16) {
        float dv[16];
#pragma unroll
        for (int u = 0; u < 16; ++u)
            dv[u] = dcol[(size_t)(k0 + u) * WK_PER_B];
#pragma unroll
        for (int u = 0; u < 16; ++u)
#pragma unroll
            for (int bb = 0; bb < 8; ++bb)
                acc[bb] = fmaf(sp[bb * 128 + k0 + u], dv[u], acc[bb]);
    }

    // j = ((ky*3+kx)*32 + ci)*32 + co
    const int tap = j >> 10, ci = (j >> 5) & 31, co = j & 31;
    const int h = ci >> 4, p = (ci >> 3) & 1;
    const int lane = ((co & 7) << 2) | ((ci >> 1) & 3);
    const int n = co >> 3, q = h * 2 + p;
    const int off_hi = (((tap * 8 + n) * 32 + lane) * 4 + q) * 4 + (ci & 1) * 2;

#pragma unroll
    for (int bb = 0; bb < 8; ++bb) {
        const float v = acc[bb];
        const __nv_bfloat16 hi = __float2bfloat16_rn(v);
        const __nv_bfloat16 lo = __float2bfloat16_rn(v - __bfloat162float(hi));
        unsigned char* base = g_wfrag + (size_t)(b0 + bb) * FRAG_B;
        *(unsigned short*)(base + off_hi)        = __bfloat16_as_ushort(hi); // ws=0
        *(unsigned short*)(base + off_hi + 2048) = __bfloat16_as_ushort(lo); // ws=1
    }
}

// ---------------------------------------------------------------------------
// Kernel 2: HMMA conv. grid (64, 32): (row-pair, batch). 256 threads, 8 warps.
// Warp w: output row r = w>>2, pixels px0 = (w&3)*32 .. +31, all 32 co.
// B fragments read directly from g_wfrag via LDG.128 (L1/L2-resident).
// 3 CTAs/SM (<=85 regs) -> 24 resident warps for latency hiding.
// ---------------------------------------------------------------------------
__global__ __launch_bounds__(256, 3)
void conv_hmma(const float* __restrict__ X, float* __restrict__ Out) {
    extern __shared__ __align__(128) unsigned char smem[];
    const int tid = threadIdx.x, wid = tid >> 5, lid = tid & 31;
    const int b = blockIdx.y;
    const int y0 = blockIdx.x * 2;

    // ---- stage X rows y0-1..y0+2 as [row][sp 0..129][hi ci32 | lo ci32] ----
    {
        const float4* Xb = (const float4*)(X + (size_t)b * HW_ * HW_ * 32);
#pragma unroll
        for (int i = tid; i < 4 * 130 * 8; i += 256) {
            const int cic = i & 7, sp = (i >> 3) % 130, ir = i / (130 * 8);
            const int gy = y0 - 1 + ir, gx = sp - 1;
            float4 v = make_float4(0.f, 0.f, 0.f, 0.f);
            if ((unsigned)gy < (unsigned)HW_ && (unsigned)gx < (unsigned)HW_)
                v = Xb[(gy * HW_ + gx) * 8 + cic];
            uint2 h, l; split4(v, h, l);
            unsigned char* rb = smem + ir * XROW_SMEM;
            const uint32_t ho = (uint32_t)(sp * 128 + cic * 8);
            *(uint2*)(rb + SWZ(ho))      = h;
            *(uint2*)(rb + SWZ(ho + 64)) = l;
        }
    }
    __syncthreads();

    const int r = wid >> 2, px0 = (wid & 3) * 32;
    // ldmatrix per-lane row/col selectors
    const int arow  = (lid & 7) + ((lid >> 3) & 1) * 8;  // pixel within 16
    const int acol8 = ((lid >> 4) & 1) * 8;              // k col within 16

    const uint32_t xbase = smem_u32(smem);
    const uint4* wsrc = (const uint4*)(g_wfrag + (size_t)b * FRAG_B) + lid;

    float acc[2][4][4];
#pragma unroll
    for (int t = 0; t < 2; ++t)
#pragma unroll
        for (int n = 0; n < 4; ++n)
#pragma unroll
            for (int c = 0; c < 4; ++c) acc[t][n][c] = 0.f;

#pragma unroll
    for (int tap = 0; tap < 9; ++tap) {
        const int ky = tap / 3, kx = tap % 3;

        // B fragments: [ws][n], 16B per lane, coalesced LDG.128 (cache hit)
        uint4 Bf[2][4];
#pragma unroll
        for (int ws = 0; ws < 2; ++ws)
#pragma unroll
            for (int n = 0; n < 4; ++n)
                Bf[ws][n] = wsrc[((tap * 2 + ws) * 4 + n) * 32];

        const uint32_t xrow = xbase + (uint32_t)((r + ky) * XROW_SMEM);
#pragma unroll
        for (int t = 0; t < 2; ++t) {
            const int spbase = px0 + t * 16 + kx;
            uint32_t A[4][4];   // s: 0=xh h0, 1=xh h1, 2=xl h0, 3=xl h1
#pragma unroll
            for (int s = 0; s < 4; ++s) {
                const uint32_t off = (uint32_t)((spbase + arow) * 128 +
                                                (s * 16 + acol8) * 2);
                ldsm4(A[s], xrow + SWZ(off));
            }
#pragma unroll
            for (int n = 0; n < 4; ++n) {
                hmma(acc[t][n], A[0], &Bf[0][n].x);   // xh h0 * wh h0
                hmma(acc[t][n], A[1], &Bf[0][n].z);   // xh h1 * wh h1
                hmma(acc[t][n], A[2], &Bf[0][n].x);   // xl h0 * wh h0
                hmma(acc[t][n], A[3], &Bf[0][n].z);   // xl h1 * wh h1
                hmma(acc[t][n], A[0], &Bf[1][n].x);   // xh h0 * wl h0
                hmma(acc[t][n], A[1], &Bf[1][n].z);   // xh h1 * wl h1
            }
        }
    }

    // ---- store C fragments: out[b][y0+r][px][co] ----
    float* outb = Out + ((size_t)b * HW_ + (size_t)(y0 + r)) * HW_ * 32;
#pragma unroll
    for (int t = 0; t < 2; ++t) {
#pragma unroll
        for (int n = 0; n < 4; ++n) {
            const int px = px0 + t * 16 + (lid >> 2);
            const int co = n * 8 + (lid & 3) * 2;
            *(float2*)(outb + px * 32 + co) =
                make_float2(acc[t][n][0], acc[t][n][1]);
            *(float2*)(outb + (px + 8) * 32 + co) =
                make_float2(acc[t][n][2], acc[t][n][3]);
        }
    }
}

// ---------------------------------------------------------------------------
extern "C" void kernel_launch(void* const* d_in, const int* in_sizes, int n_in,
                              void* d_out, int out_size) {
    const float* X  = (const float*)d_in[0];
    const float* P  = (const float*)d_in[1];
    const float* Dw = (const float*)d_in[2];
    float* Out = (float*)d_out;

    wgemm_kernel<<<dim3(36, 4), 256>>>(P, Dw);

    cudaFuncSetAttribute(conv_hmma, cudaFuncAttributeMaxDynamicSharedMemorySize,
                         SMEM_TOTAL);
    conv_hmma<<<dim3(HW_ / 2, B_), 256, SMEM_TOTAL>>>(X, Out);
}

// round 8
// speedup vs baseline: 1.8738x; 1.8738x over previous
#include <cuda_runtime.h>
#include <cuda_bf16.h>
#include <cstdint>

// ---------------------------------------------------------------------------
// ConditionedConvolution2D via mma.sync bf16 (3-term split, fp32 accumulate)
//   X [32,128,128,32] f32 NHWC, P [32,128] f32, dense_w [128,9216] f32
//   A = P @ dense_w -> Wk[32,3,3,32,32];  out[b] = conv2d_same(X[b], Wk[b])
// x = xh + xl (bf16), w = wh + wl (bf16); out ~= xh*wh + xh*wl + xl*wh.
// ---------------------------------------------------------------------------

#define B_       32
#define HW_      128
#define WK_PER_B 9216
#define FRAG_B   36864      // bytes of packed bf16 B-fragments per batch
#define XROW_SMEM 16640     // 130 px * 128 B (hi|lo * 32 ci bf16)
#define SMEM_TOTAL (4 * XROW_SMEM)   // 66560

__device__ unsigned char g_wfrag[B_ * FRAG_B];

// SW128 swizzle (row stride 128B): XOR bits[4:6] with bits[7:9]
#define SWZ(o) ((o) ^ (((o) >> 3) & 0x70))

__device__ __forceinline__ uint32_t smem_u32(const void* p) {
    uint32_t a;
    asm("{ .reg .u64 t; cvta.to.shared.u64 t, %1; cvt.u32.u64 %0, t; }"
        : "=r"(a) : "l"(p));
    return a;
}
__device__ __forceinline__ void ldsm4(uint32_t* r, uint32_t addr) {
    asm volatile("ldmatrix.sync.aligned.m8n8.x4.shared.b16 {%0,%1,%2,%3}, [%4];"
        : "=r"(r[0]), "=r"(r[1]), "=r"(r[2]), "=r"(r[3]) : "r"(addr));
}
__device__ __forceinline__ void hmma(float* c, const uint32_t* a, const uint32_t* b) {
    asm volatile("mma.sync.aligned.m16n8k16.row.col.f32.bf16.bf16.f32 "
        "{%0,%1,%2,%3}, {%4,%5,%6,%7}, {%8,%9}, {%0,%1,%2,%3};"
        : "+f"(c[0]), "+f"(c[1]), "+f"(c[2]), "+f"(c[3])
        : "r"(a[0]), "r"(a[1]), "r"(a[2]), "r"(a[3]), "r"(b[0]), "r"(b[1]));
}
__device__ __forceinline__ uint32_t pk(__nv_bfloat16 a, __nv_bfloat16 b) {
    return (uint32_t)__bfloat16_as_ushort(a) | ((uint32_t)__bfloat16_as_ushort(b) << 16);
}
__device__ __forceinline__ void split4(float4 v, uint2& h, uint2& l) {
    __nv_bfloat16 hx = __float2bfloat16_rn(v.x), hy = __float2bfloat16_rn(v.y);
    __nv_bfloat16 hz = __float2bfloat16_rn(v.z), hw = __float2bfloat16_rn(v.w);
    h.x = pk(hx, hy); h.y = pk(hz, hw);
    l.x = pk(__float2bfloat16_rn(v.x - __bfloat162float(hx)),
             __float2bfloat16_rn(v.y - __bfloat162float(hy)));
    l.y = pk(__float2bfloat16_rn(v.z - __bfloat162float(hz)),
             __float2bfloat16_rn(v.w - __bfloat162float(hw)));
}

// ---------------------------------------------------------------------------
// Kernel 1: hypernetwork GEMM; writes wh/wl bf16 directly in mma-B fragment
// layout:  g_wfrag[b][tap][ws][n][lane][4 x u32]
// grid (36, 4), 256 threads; each block handles 8 batches.
// k-loop unrolled by 32 -> 32 outstanding DRAM loads, 4 dependent rounds.
// ---------------------------------------------------------------------------
__global__ __launch_bounds__(256)
void wgemm_kernel(const float* __restrict__ P, const float* __restrict__ Dw) {
    __shared__ float sp[1024];
    const int b0 = blockIdx.y * 8;
    const int j  = blockIdx.x * 256 + threadIdx.x;    // 0..9215

    for (int i = threadIdx.x; i < 1024; i += 256) sp[i] = P[b0 * 128 + i];
    __syncthreads();

    float acc[8];
#pragma unroll
    for (int bb = 0; bb < 8; ++bb) acc[bb] = 0.f;

    const float* dcol = Dw + j;
#pragma unroll
    for (int k0 = 0; k0 < 128; k0 += 32) {
        float dv[32];
#pragma unroll
        for (int u = 0; u < 32; ++u)
            dv[u] = dcol[(size_t)(k0 + u) * WK_PER_B];
#pragma unroll
        for (int u = 0; u < 32; ++u)
#pragma unroll
            for (int bb = 0; bb < 8; ++bb)
                acc[bb] = fmaf(sp[bb * 128 + k0 + u], dv[u], acc[bb]);
    }

    // j = ((ky*3+kx)*32 + ci)*32 + co
    const int tap = j >> 10, ci = (j >> 5) & 31, co = j & 31;
    const int h = ci >> 4, p = (ci >> 3) & 1;
    const int lane = ((co & 7) << 2) | ((ci >> 1) & 3);
    const int n = co >> 3, q = h * 2 + p;
    const int off_hi = (((tap * 8 + n) * 32 + lane) * 4 + q) * 4 + (ci & 1) * 2;

#pragma unroll
    for (int bb = 0; bb < 8; ++bb) {
        const float v = acc[bb];
        const __nv_bfloat16 hi = __float2bfloat16_rn(v);
        const __nv_bfloat16 lo = __float2bfloat16_rn(v - __bfloat162float(hi));
        unsigned char* base = g_wfrag + (size_t)(b0 + bb) * FRAG_B;
        *(unsigned short*)(base + off_hi)        = __bfloat16_as_ushort(hi); // ws=0
        *(unsigned short*)(base + off_hi + 2048) = __bfloat16_as_ushort(lo); // ws=1
    }
}

// ---------------------------------------------------------------------------
// Kernel 2: HMMA conv. grid (64, 32): (row-pair, batch). 256 threads, 8 warps.
// Warp w: output row r = w>>2, pixels px0 = (w&3)*32 .. +31, all 32 co.
// Per tap: batch all 8 B-LDGs + all 8 A-ldsms (both t tiles), then 96 HMMAs.
// ---------------------------------------------------------------------------
__global__ __launch_bounds__(256, 2)
void conv_hmma(const float* __restrict__ X, float* __restrict__ Out) {
    extern __shared__ __align__(128) unsigned char smem[];
    const int tid = threadIdx.x, wid = tid >> 5, lid = tid & 31;
    const int b = blockIdx.y;
    const int y0 = blockIdx.x * 2;

    // ---- stage X rows y0-1..y0+2 as [row][sp 0..129][hi ci32 | lo ci32] ----
    {
        const float4* Xb = (const float4*)(X + (size_t)b * HW_ * HW_ * 32);
#pragma unroll
        for (int i = tid; i < 4 * 130 * 8; i += 256) {
            const int cic = i & 7, sp = (i >> 3) % 130, ir = i / (130 * 8);
            const int gy = y0 - 1 + ir, gx = sp - 1;
            float4 v = make_float4(0.f, 0.f, 0.f, 0.f);
            if ((unsigned)gy < (unsigned)HW_ && (unsigned)gx < (unsigned)HW_)
                v = Xb[(gy * HW_ + gx) * 8 + cic];
            uint2 h, l; split4(v, h, l);
            unsigned char* rb = smem + ir * XROW_SMEM;
            const uint32_t ho = (uint32_t)(sp * 128 + cic * 8);
            *(uint2*)(rb + SWZ(ho))      = h;
            *(uint2*)(rb + SWZ(ho + 64)) = l;
        }
    }
    __syncthreads();

    const int r = wid >> 2, px0 = (wid & 3) * 32;
    // ldmatrix per-lane row/col selectors
    const int arow  = (lid & 7) + ((lid >> 3) & 1) * 8;  // pixel within 16
    const int acol8 = ((lid >> 4) & 1) * 8;              // k col within 16

    const uint32_t xbase = smem_u32(smem);
    const uint4* wsrc = (const uint4*)(g_wfrag + (size_t)b * FRAG_B) + lid;

    float acc[2][4][4];
#pragma unroll
    for (int t = 0; t < 2; ++t)
#pragma unroll
        for (int n = 0; n < 4; ++n)
#pragma unroll
            for (int c = 0; c < 4; ++c) acc[t][n][c] = 0.f;

#pragma unroll
    for (int tap = 0; tap < 9; ++tap) {
        const int ky = tap / 3, kx = tap % 3;

        // ---- B fragments first: 8 independent LDG.128 (cache hits) ----
        uint4 Bf[2][4];
#pragma unroll
        for (int ws = 0; ws < 2; ++ws)
#pragma unroll
            for (int n = 0; n < 4; ++n)
                Bf[ws][n] = wsrc[((tap * 2 + ws) * 4 + n) * 32];

        // ---- A fragments for BOTH t tiles: 8 independent ldsm.x4 ----
        const uint32_t xrow = xbase + (uint32_t)((r + ky) * XROW_SMEM);
        uint32_t A[2][4][4];   // [t][s], s: 0=xh h0, 1=xh h1, 2=xl h0, 3=xl h1
#pragma unroll
        for (int t = 0; t < 2; ++t) {
            const int spbase = px0 + t * 16 + kx;
#pragma unroll
            for (int s = 0; s < 4; ++s) {
                const uint32_t off = (uint32_t)((spbase + arow) * 128 +
                                                (s * 16 + acol8) * 2);
                ldsm4(A[t][s], xrow + SWZ(off));
            }
        }

        // ---- 96 HMMAs ----
#pragma unroll
        for (int t = 0; t < 2; ++t) {
#pragma unroll
            for (int n = 0; n < 4; ++n) {
                hmma(acc[t][n], A[t][0], &Bf[0][n].x);   // xh h0 * wh h0
                hmma(acc[t][n], A[t][1], &Bf[0][n].z);   // xh h1 * wh h1
                hmma(acc[t][n], A[t][2], &Bf[0][n].x);   // xl h0 * wh h0
                hmma(acc[t][n], A[t][3], &Bf[0][n].z);   // xl h1 * wh h1
                hmma(acc[t][n], A[t][0], &Bf[1][n].x);   // xh h0 * wl h0
                hmma(acc[t][n], A[t][1], &Bf[1][n].z);   // xh h1 * wl h1
            }
        }
    }

    // ---- store C fragments: out[b][y0+r][px][co] ----
    float* outb = Out + ((size_t)b * HW_ + (size_t)(y0 + r)) * HW_ * 32;
#pragma unroll
    for (int t = 0; t < 2; ++t) {
#pragma unroll
        for (int n = 0; n < 4; ++n) {
            const int px = px0 + t * 16 + (lid >> 2);
            const int co = n * 8 + (lid & 3) * 2;
            *(float2*)(outb + px * 32 + co) =
                make_float2(acc[t][n][0], acc[t][n][1]);
            *(float2*)(outb + (px + 8) * 32 + co) =
                make_float2(acc[t][n][2], acc[t][n][3]);
        }
    }
}

// ---------------------------------------------------------------------------
extern "C" void kernel_launch(void* const* d_in, const int* in_sizes, int n_in,
                              void* d_out, int out_size) {
    const float* X  = (const float*)d_in[0];
    const float* P  = (const float*)d_in[1];
    const float* Dw = (const float*)d_in[2];
    float* Out = (float*)d_out;

    wgemm_kernel<<<dim3(36, 4), 256>>>(P, Dw);

    cudaFuncSetAttribute(conv_hmma, cudaFuncAttributeMaxDynamicSharedMemorySize,
                         SMEM_TOTAL);
    conv_hmma<<<dim3(HW_ / 2, B_), 256, SMEM_TOTAL>>>(X, Out);
}

// round 9
// speedup vs baseline: 2.8523x; 1.5222x over previous
#include <cuda_runtime.h>
#include <cuda_fp16.h>
#include <cstdint>

// ---------------------------------------------------------------------------
// ConditionedConvolution2D via mma.sync fp16 single-term (fp32 accumulate)
//   X [32,128,128,32] f32 NHWC, P [32,128] f32, dense_w [128,9216] f32
//   A = P @ dense_w -> Wk[32,3,3,32,32];  out[b] = conv2d_same(X[b], Wk[b])
// x ~ fp16(x), w ~ fp16(w): per-product rel error ~2^-12 -> global ~1.5e-4.
// ---------------------------------------------------------------------------

#define B_       32
#define HW_      128
#define WK_PER_B 9216
#define FRAG_B   18432      // bytes of packed fp16 B-fragments per batch
#define XROW_SMEM 10400     // 130 px * 80 B (32 ci fp16 = 64B, stride 80)
#define SMEM_TOTAL (4 * XROW_SMEM)   // 41600

__device__ uint4 g_wfrag4[B_ * FRAG_B / 16];

__device__ __forceinline__ uint32_t smem_u32(const void* p) {
    uint32_t a;
    asm("{ .reg .u64 t; cvta.to.shared.u64 t, %1; cvt.u32.u64 %0, t; }"
        : "=r"(a) : "l"(p));
    return a;
}
__device__ __forceinline__ void ldsm4(uint32_t* r, uint32_t addr) {
    asm volatile("ldmatrix.sync.aligned.m8n8.x4.shared.b16 {%0,%1,%2,%3}, [%4];"
        : "=r"(r[0]), "=r"(r[1]), "=r"(r[2]), "=r"(r[3]) : "r"(addr));
}
__device__ __forceinline__ void hmma(float* c, const uint32_t* a, const uint32_t* b) {
    asm volatile("mma.sync.aligned.m16n8k16.row.col.f32.f16.f16.f32 "
        "{%0,%1,%2,%3}, {%4,%5,%6,%7}, {%8,%9}, {%0,%1,%2,%3};"
        : "+f"(c[0]), "+f"(c[1]), "+f"(c[2]), "+f"(c[3])
        : "r"(a[0]), "r"(a[1]), "r"(a[2]), "r"(a[3]), "r"(b[0]), "r"(b[1]));
}
__device__ __forceinline__ uint32_t pkh(float a, float b) {
    __half2 h = __floats2half2_rn(a, b);
    return *reinterpret_cast<uint32_t*>(&h);
}

// ---------------------------------------------------------------------------
// Kernel 1: hypernetwork GEMM; writes fp16 weights directly in mma-B fragment
// layout:  g_wfrag[b][tap][n][lane][4 x u32]  (q = (ci>>4)*2 + ((ci>>3)&1))
// grid (36, 4), 256 threads; each block handles 8 batches.
// ---------------------------------------------------------------------------
__global__ __launch_bounds__(256)
void wgemm_kernel(const float* __restrict__ P, const float* __restrict__ Dw) {
    __shared__ float sp[1024];
    const int b0 = blockIdx.y * 8;
    const int j  = blockIdx.x * 256 + threadIdx.x;    // 0..9215

    for (int i = threadIdx.x; i < 1024; i += 256) sp[i] = P[b0 * 128 + i];
    __syncthreads();

    float acc[8];
#pragma unroll
    for (int bb = 0; bb < 8; ++bb) acc[bb] = 0.f;

    const float* dcol = Dw + j;
#pragma unroll
    for (int k0 = 0; k0 < 128; k0 += 32) {
        float dv[32];
#pragma unroll
        for (int u = 0; u < 32; ++u)
            dv[u] = dcol[(size_t)(k0 + u) * WK_PER_B];
#pragma unroll
        for (int u = 0; u < 32; ++u)
#pragma unroll
            for (int bb = 0; bb < 8; ++bb)
                acc[bb] = fmaf(sp[bb * 128 + k0 + u], dv[u], acc[bb]);
    }

    // j = ((ky*3+kx)*32 + ci)*32 + co
    const int tap = j >> 10, ci = (j >> 5) & 31, co = j & 31;
    const int h = ci >> 4, p = (ci >> 3) & 1;
    const int lane = ((co & 7) << 2) | ((ci >> 1) & 3);
    const int n = co >> 3, q = h * 2 + p;
    const int off = (((tap * 4 + n) * 32 + lane) * 4 + q) * 4 + (ci & 1) * 2;

#pragma unroll
    for (int bb = 0; bb < 8; ++bb) {
        const __half hv = __float2half_rn(acc[bb]);
        unsigned char* base =
            reinterpret_cast<unsigned char*>(g_wfrag4) + (size_t)(b0 + bb) * FRAG_B;
        *(unsigned short*)(base + off) = *(const unsigned short*)&hv;
    }
}

// ---------------------------------------------------------------------------
// Kernel 2: HMMA conv. grid (64, 32): (row-pair, batch). 256 threads, 8 warps.
// Warp w: output row r = w>>2, pixels px0 = (w&3)*32 .. +31, all 32 co.
// Per tap: 4 B-LDG.128 + 4 A-ldsm.x4 + 16 HMMA. ~80 regs -> 3 CTAs/SM.
// X staged at 80B/px stride: (5*px mod 8) hits all 16B bank-groups, no swizzle.
// ---------------------------------------------------------------------------
__global__ __launch_bounds__(256, 3)
void conv_hmma(const float* __restrict__ X, float* __restrict__ Out) {
    extern __shared__ __align__(128) unsigned char smem[];
    const int tid = threadIdx.x, wid = tid >> 5, lid = tid & 31;
    const int b = blockIdx.y;
    const int y0 = blockIdx.x * 2;

    // ---- stage X rows y0-1..y0+2 as [row][sp 0..129][32 ci fp16] ----
    {
        const float4* Xb = (const float4*)(X + (size_t)b * HW_ * HW_ * 32);
#pragma unroll
        for (int i = tid; i < 4 * 130 * 8; i += 256) {
            const int cic = i & 7, sp = (i >> 3) % 130, ir = i / (130 * 8);
            const int gy = y0 - 1 + ir, gx = sp - 1;
            float4 v = make_float4(0.f, 0.f, 0.f, 0.f);
            if ((unsigned)gy < (unsigned)HW_ && (unsigned)gx < (unsigned)HW_)
                v = Xb[(gy * HW_ + gx) * 8 + cic];
            uint2 hh;
            hh.x = pkh(v.x, v.y);
            hh.y = pkh(v.z, v.w);
            *(uint2*)(smem + ir * XROW_SMEM + sp * 80 + cic * 8) = hh;
        }
    }
    __syncthreads();

    const int r = wid >> 2, px0 = (wid & 3) * 32;
    // ldmatrix per-lane row/col selectors
    const int arow  = (lid & 7) + ((lid >> 3) & 1) * 8;  // pixel within 16
    const int acol8 = ((lid >> 4) & 1) * 8;              // k col within 16

    const uint32_t xbase = smem_u32(smem);
    const uint4* wsrc =
        g_wfrag4 + (size_t)b * (FRAG_B / 16) + lid;

    float acc[2][4][4];
#pragma unroll
    for (int t = 0; t < 2; ++t)
#pragma unroll
        for (int n = 0; n < 4; ++n)
#pragma unroll
            for (int c = 0; c < 4; ++c) acc[t][n][c] = 0.f;

#pragma unroll
    for (int tap = 0; tap < 9; ++tap) {
        const int ky = tap / 3, kx = tap % 3;

        // ---- B fragments: 4 independent LDG.128 (cache hits) ----
        uint4 Bf[4];
#pragma unroll
        for (int n = 0; n < 4; ++n)
            Bf[n] = wsrc[(tap * 4 + n) * 32];

        // ---- A fragments, both t tiles: 4 independent ldsm.x4 ----
        const uint32_t xrow = xbase + (uint32_t)((r + ky) * XROW_SMEM);
        uint32_t A[2][2][4];   // [t][s], s = k-tile (ci 0-15 / 16-31)
#pragma unroll
        for (int t = 0; t < 2; ++t) {
            const int spx = px0 + t * 16 + kx + arow;
#pragma unroll
            for (int s = 0; s < 2; ++s)
                ldsm4(A[t][s], xrow + (uint32_t)(spx * 80 + s * 32 + acol8 * 2));
        }

        // ---- 16 HMMAs ----
#pragma unroll
        for (int t = 0; t < 2; ++t) {
#pragma unroll
            for (int n = 0; n < 4; ++n) {
                hmma(acc[t][n], A[t][0], &Bf[n].x);   // k-tile 0
                hmma(acc[t][n], A[t][1], &Bf[n].z);   // k-tile 1
            }
        }
    }

    // ---- store C fragments: out[b][y0+r][px][co] ----
    float* outb = Out + ((size_t)b * HW_ + (size_t)(y0 + r)) * HW_ * 32;
#pragma unroll
    for (int t = 0; t < 2; ++t) {
#pragma unroll
        for (int n = 0; n < 4; ++n) {
            const int px = px0 + t * 16 + (lid >> 2);
            const int co = n * 8 + (lid & 3) * 2;
            *(float2*)(outb + px * 32 + co) =
                make_float2(acc[t][n][0], acc[t][n][1]);
            *(float2*)(outb + (px + 8) * 32 + co) =
                make_float2(acc[t][n][2], acc[t][n][3]);
        }
    }
}

// ---------------------------------------------------------------------------
extern "C" void kernel_launch(void* const* d_in, const int* in_sizes, int n_in,
                              void* d_out, int out_size) {
    const float* X  = (const float*)d_in[0];
    const float* P  = (const float*)d_in[1];
    const float* Dw = (const float*)d_in[2];
    float* Out = (float*)d_out;

    wgemm_kernel<<<dim3(36, 4), 256>>>(P, Dw);

    cudaFuncSetAttribute(conv_hmma, cudaFuncAttributeMaxDynamicSharedMemorySize,
                         SMEM_TOTAL);
    conv_hmma<<<dim3(HW_ / 2, B_), 256, SMEM_TOTAL>>>(X, Out);
}